// round 9
// baseline (speedup 1.0000x reference)
#include <cuda_runtime.h>
#include <cuda_fp16.h>

// Problem constants (fixed shapes for this problem)
#define N_NODES 20000
#define F_IN    8
#define T_P     12
#define HID     32
#define FEAT    96      // F_IN * T_P floats per node
#define FEAT4   24      // FEAT / 4

// ---------------- device scratch (no allocations allowed) ----------------
__device__ float  g_cnt [N_NODES];               // edge in-degree (zeroed by memset)
__device__ float  g_dinv[N_NODES];               // rsqrt(cnt + 1)
__device__ float4 g_agg [N_NODES * FEAT4];       // dinv_d*x_d + sum_e dinv_s*x_s
__device__ __half g_xh  [N_NODES * FEAT];        // fp16(dinv_n * x_n)
__device__ float  g_WLz [F_IN * HID];            // Wz @ Lz_top  (8 x 32)
__device__ float  g_WLh [F_IN * HID];            // Wh @ Lh_top  (8 x 32)
__device__ float  g_blz [HID];                   // bz @ Lz_top + lz
__device__ float  g_blh [HID];                   // bh @ Lh_top + lh
__device__ float  g_probs[T_P];                  // softmax(att)

__device__ __forceinline__ float fast_tanh(float x) {
    float y;
    asm("tanh.approx.f32 %0, %1;" : "=f"(y) : "f"(x));
    return y;
}

// ---- packed f32x2 helpers (Blackwell; exact fp32, 1 instr = 2 FMAs) ----
__device__ __forceinline__ unsigned long long pack2(float a, float b) {
    unsigned long long r;
    asm("mov.b64 %0, {%1, %2};" : "=l"(r) : "f"(a), "f"(b));
    return r;
}
__device__ __forceinline__ void unpack2(unsigned long long v, float& a, float& b) {
    asm("mov.b64 {%0, %1}, %2;" : "=f"(a), "=f"(b) : "l"(v));
}
__device__ __forceinline__ unsigned long long fma2(unsigned long long a,
                                                   unsigned long long b,
                                                   unsigned long long c) {
    unsigned long long r;
    asm("fma.rn.f32x2 %0, %1, %2, %3;" : "=l"(r) : "l"(a), "l"(b), "l"(c));
    return r;
}
__device__ __forceinline__ unsigned long long mul2(unsigned long long a,
                                                   unsigned long long b) {
    unsigned long long r;
    asm("mul.rn.f32x2 %0, %1, %2;" : "=l"(r) : "l"(a), "l"(b));
    return r;
}

// ---------------- kernels ----------------

// Degree histogram (4 edges/thread). Block 0 additionally folds the gate
// weights (WL = W @ L_top, bl = b @ L_top + l) and computes softmax(att).
__global__ void k_count_pre(const int4* __restrict__ dst4, int E4,
                            const float* __restrict__ Wz, const float* __restrict__ bz,
                            const float* __restrict__ Wh, const float* __restrict__ bh,
                            const float* __restrict__ Lz, const float* __restrict__ lz,
                            const float* __restrict__ Lh, const float* __restrict__ lh,
                            const float* __restrict__ att) {
    int i = blockIdx.x * blockDim.x + threadIdx.x;
    if (i < E4) {
        int4 d = __ldg(&dst4[i]);
        atomicAdd(&g_cnt[d.x], 1.0f);
        atomicAdd(&g_cnt[d.y], 1.0f);
        atomicAdd(&g_cnt[d.z], 1.0f);
        atomicAdd(&g_cnt[d.w], 1.0f);
    }
    if (blockIdx.x == 0) {
        int tid = threadIdx.x;
        if (tid < F_IN * HID) {
            int f = tid >> 5, h = tid & 31;
            float az = 0.f, ah = 0.f;
            #pragma unroll 8
            for (int k = 0; k < HID; k++) {
                az = fmaf(Wz[f * HID + k], Lz[k * HID + h], az);
                ah = fmaf(Wh[f * HID + k], Lh[k * HID + h], ah);
            }
            g_WLz[tid] = az;
            g_WLh[tid] = ah;
        }
        if (tid < HID) {
            float az = lz[tid], ah = lh[tid];
            for (int k = 0; k < HID; k++) {
                az = fmaf(bz[k], Lz[k * HID + tid], az);
                ah = fmaf(bh[k], Lh[k * HID + tid], ah);
            }
            g_blz[tid] = az;
            g_blh[tid] = ah;
        }
        if (tid == 0) {
            float m = -1e30f;
            for (int t = 0; t < T_P; t++) m = fmaxf(m, att[t]);
            float e[T_P], s = 0.f;
            for (int t = 0; t < T_P; t++) { e[t] = __expf(att[t] - m); s += e[t]; }
            float inv = 1.0f / s;
            for (int t = 0; t < T_P; t++) g_probs[t] = e[t] * inv;
        }
    }
}

// Node-indexed mid pass: dinv, seed agg with self term (dinv*x, plain stores
// -> no agg memset needed), and write fp16 pre-scaled features for the scatter.
__global__ void k_mid(const float4* __restrict__ x4) {
    int i = blockIdx.x * blockDim.x + threadIdx.x;
    if (i >= N_NODES * FEAT4) return;
    int n = i / FEAT4;
    float dn = rsqrtf(__ldg(&g_cnt[n]) + 1.0f);
    if ((i - n * FEAT4) == 0) g_dinv[n] = dn;
    float4 v = __ldg(&x4[i]);
    v.x *= dn; v.y *= dn; v.z *= dn; v.w *= dn;
    g_agg[i] = v;                                 // self-loop seed (x dinv scale)
    __half2* xh2 = (__half2*)g_xh;
    xh2[i * 2]     = __floats2half2_rn(v.x, v.y);
    xh2[i * 2 + 1] = __floats2half2_rn(v.z, v.w);
}

// Scatter: agg[dst] += xh[src] (already dinv_s-scaled, fp16 -> f32 reds).
// 8 threads per edge; lane owns chunks sub, sub+8, sub+16 so each red.v4
// wavefront (8 lanes x 16B) covers one contiguous 128B segment of agg[dst].
__global__ void k_scatter(const int* __restrict__ src,
                          const int* __restrict__ dst, int E) {
    int i = blockIdx.x * blockDim.x + threadIdx.x;
    int e = i >> 3;
    if (e >= E) return;
    int sub = i & 7;
    int s = __ldg(&src[e]);
    int d = __ldg(&dst[e]);

    const uint2* xh2 = (const uint2*)g_xh + s * FEAT4;  // 24 x 8B = 96 halves
    float4* ad = g_agg + d * FEAT4;
    #pragma unroll
    for (int k = 0; k < 3; k++) {
        int c = sub + k * 8;                      // chunk index 0..23
        uint2 hv = __ldg(&xh2[c]);
        float2 f0 = __half22float2(*(const __half2*)&hv.x);
        float2 f1 = __half22float2(*(const __half2*)&hv.y);
        asm volatile("red.global.add.v4.f32 [%0], {%1, %2, %3, %4};"
                     :: "l"(&ad[c]), "f"(f0.x), "f"(f0.y), "f"(f1.x), "f"(f1.y)
                     : "memory");
    }
}

// One warp per node. Feature-major smem (no transpose); gate matmul in
// packed f32x2 (t-pairs), tanh epilogue, attention, output projection.
__global__ void __launch_bounds__(256)
k_node(const float* __restrict__ Wout,
       const float* __restrict__ bout,
       float* __restrict__ out) {
    __shared__ float sh[8][FEAT];                // feature-major, per warp
    __shared__ float sWout[HID * T_P];
    __shared__ float sBout[T_P];

    const int tid  = threadIdx.x;
    const int w    = tid >> 5;
    const int lane = tid & 31;

    for (int i = tid; i < HID * T_P; i += 256) sWout[i] = Wout[i];
    if (tid < T_P) sBout[tid] = bout[tid];
    __syncthreads();

    const int node = blockIdx.x * 8 + w;         // 2500 blocks * 8 warps = 20000

    const float dn = g_dinv[node];

    // lanes 0..23: scale one float4 chunk and store straight (feature-major).
    if (lane < FEAT4) {
        float4 A = g_agg[node * FEAT4 + lane];
        A.x *= dn; A.y *= dn; A.z *= dn; A.w *= dn;
        ((float4*)sh[w])[lane] = A;
    }
    __syncwarp();

    // Packed gate weights (lane == hidden index h), duplicated into f32x2.
    unsigned long long wzd[F_IN], whd[F_IN];
    #pragma unroll
    for (int f = 0; f < F_IN; f++) {
        float a = g_WLz[f * HID + lane];
        float b = g_WLh[f * HID + lane];
        wzd[f] = pack2(a, a);
        whd[f] = pack2(b, b);
    }
    const float bz0 = g_blz[lane];
    const float bh0 = g_blh[lane];
    const unsigned long long bzd = pack2(bz0, bz0);
    const unsigned long long bhd = pack2(bh0, bh0);
    const unsigned long long hfd = pack2(0.5f, 0.5f);

    float hacc = 0.f;
    #pragma unroll
    for (int q = 0; q < 3; q++) {                // t-quads: t = 4q..4q+3
        unsigned long long uz0 = bzd, uz1 = bzd;
        unsigned long long uh0 = bhd, uh1 = bhd;
        #pragma unroll
        for (int f = 0; f < F_IN; f++) {
            // 4 consecutive t-values of feature f (16B-aligned: 48f + 16q).
            ulonglong2 xa = *(const ulonglong2*)&sh[w][f * T_P + q * 4];
            uz0 = fma2(xa.x, wzd[f], uz0);
            uz1 = fma2(xa.y, wzd[f], uz1);
            uh0 = fma2(xa.x, whd[f], uh0);
            uh1 = fma2(xa.y, whd[f], uh1);
        }
        uz0 = mul2(uz0, hfd);                    // 0.5 * uz (for sigmoid-as-tanh)
        uz1 = mul2(uz1, hfd);
        float z0, z1, z2, z3, h0, h1, h2, h3;
        unpack2(uz0, z0, z1); unpack2(uz1, z2, z3);
        unpack2(uh0, h0, h1); unpack2(uh1, h2, h3);
        // (1 - sigmoid(u)) = 0.5 - 0.5*tanh(u/2)
        float o0 = fmaf(-0.5f, fast_tanh(z0), 0.5f);
        float o1 = fmaf(-0.5f, fast_tanh(z1), 0.5f);
        float o2 = fmaf(-0.5f, fast_tanh(z2), 0.5f);
        float o3 = fmaf(-0.5f, fast_tanh(z3), 0.5f);
        hacc = fmaf(g_probs[q * 4 + 0], o0 * fast_tanh(h0), hacc);
        hacc = fmaf(g_probs[q * 4 + 1], o1 * fast_tanh(h1), hacc);
        hacc = fmaf(g_probs[q * 4 + 2], o2 * fast_tanh(h2), hacc);
        hacc = fmaf(g_probs[q * 4 + 3], o3 * fast_tanh(h3), hacc);
    }

    __syncwarp();
    sh[w][lane] = fmaxf(hacc, 0.f);              // relu(H_accum)
    __syncwarp();

    if (lane < T_P) {
        float acc = sBout[lane];
        #pragma unroll
        for (int h = 0; h < HID; h++)
            acc = fmaf(sh[w][h], sWout[h * T_P + lane], acc);
        out[node * T_P + lane] = acc;
    }
}

// ---------------- launch ----------------
extern "C" void kernel_launch(void* const* d_in, const int* in_sizes, int n_in,
                              void* d_out, int out_size) {
    const float* x    = (const float*)d_in[0];   // (N, F_IN, T)
    const int*   ei   = (const int*)  d_in[1];   // (2, E)
    const float* Wz   = (const float*)d_in[2];
    const float* bz   = (const float*)d_in[3];
    // d_in[4], d_in[5]: Wr, br  (dead: H0 == 0)
    const float* Wh   = (const float*)d_in[6];
    const float* bh   = (const float*)d_in[7];
    const float* Lz   = (const float*)d_in[8];
    const float* lz   = (const float*)d_in[9];
    // d_in[10], d_in[11]: Lr, lr (dead)
    const float* Lh   = (const float*)d_in[12];
    const float* lh   = (const float*)d_in[13];
    const float* att  = (const float*)d_in[14];
    const float* Wout = (const float*)d_in[15];
    const float* bout = (const float*)d_in[16];
    float* out = (float*)d_out;

    int E = in_sizes[1] / 2;
    const int* src = ei;
    const int* dst = ei + E;

    // Zero only the degree histogram (agg is fully overwritten by k_mid).
    void* cptr = nullptr;
    cudaGetSymbolAddress(&cptr, g_cnt);
    cudaMemsetAsync(cptr, 0, (size_t)N_NODES * sizeof(float));

    int E4 = E / 4;
    k_count_pre<<<(E4 + 255) / 256, 256>>>((const int4*)dst, E4,
                                           Wz, bz, Wh, bh, Lz, lz, Lh, lh, att);

    k_mid<<<(N_NODES * FEAT4 + 255) / 256, 256>>>((const float4*)x);

    k_scatter<<<(E * 8 + 255) / 256, 256>>>(src, dst, E);

    k_node<<<(N_NODES + 7) / 8, 256>>>(Wout, bout, out);
}